// round 3
// baseline (speedup 1.0000x reference)
#include <cuda_runtime.h>

// Problem shape (fixed by reference setup_inputs)
#define NB   4
#define NC   19
#define HH   512
#define WW   1024
#define HWX  (HH * WW)        // 524288 = 2^19
#define NPIX (NB * HWX)       // 2097152 = 2^21
#define MIN_KEPT_K 100000

// ---------------- device scratch (no allocations allowed) ----------------
__device__ float        g_loss[NPIX];       // 8 MB loss scratch
__device__ unsigned int g_hist[256];
__device__ unsigned int g_nvalid;
__device__ unsigned int g_prefix;           // radix-select accumulated bits
__device__ unsigned int g_k;                // remaining rank
__device__ double       g_total_sum;        // fallback mean numerator
__device__ double       g_kept_sum;
__device__ unsigned int g_kept_cnt;

// ---------------- kernels ----------------
__global__ void init_kernel() {
    int t = threadIdx.x;
    g_hist[t] = 0u;
    if (t == 0) {
        g_nvalid   = 0u;
        g_prefix   = 0u;
        g_k        = 0u;
        g_total_sum = 0.0;
        g_kept_sum  = 0.0;
        g_kept_cnt  = 0u;
    }
}

// Fused: per-pixel NLL (logsumexp - gathered logit), loss scratch write,
// validity count, fallback total sum, and histogram of top 8 bits.
__global__ void __launch_bounds__(256) loss_kernel(
    const float* __restrict__ logits,
    const int* __restrict__ targets)          // int32 (jax x64 disabled)
{
    __shared__ unsigned int sh[256];
    __shared__ unsigned int sval;
    __shared__ float wsum[8];

    const int t = threadIdx.x;
    sh[t] = 0u;
    if (t == 0) sval = 0u;
    __syncthreads();

    const int idx = blockIdx.x * 256 + t;     // grid sized exactly NPIX/256
    const int n  = idx >> 19;                 // idx / HWX
    const int hw = idx & (HWX - 1);

    const float* base = logits + ((size_t)n * NC) * HWX + hw;

    float v[NC];
    #pragma unroll
    for (int c = 0; c < NC; c++)
        v[c] = __ldg(base + (size_t)c * HWX);

    float m = v[0];
    #pragma unroll
    for (int c = 1; c < NC; c++) m = fmaxf(m, v[c]);

    float s = 0.0f;
    #pragma unroll
    for (int c = 0; c < NC; c++) s += expf(v[c] - m);

    const int tg = targets[idx];
    // unrolled select (avoids dynamic register-array index -> local mem spill)
    float xt = v[0];
    #pragma unroll
    for (int c = 1; c < NC; c++) xt = (tg == c) ? v[c] : xt;

    const float loss = m + logf(s) - xt;
    g_loss[idx] = loss;

    if (loss > 0.0f) {
        atomicAdd(&sh[__float_as_uint(loss) >> 24], 1u);
        atomicAdd(&sval, 1u);
    }

    // block-reduce total sum (for the n_valid==0 fallback path)
    float ls = loss;
    #pragma unroll
    for (int o = 16; o; o >>= 1) ls += __shfl_down_sync(0xffffffffu, ls, o);
    if ((t & 31) == 0) wsum[t >> 5] = ls;
    __syncthreads();
    if (t < 8) {
        float x = wsum[t];
        #pragma unroll
        for (int o = 4; o; o >>= 1) x += __shfl_down_sync(0xffu, x, o);
        if (t == 0) atomicAdd(&g_total_sum, (double)x);
    }

    if (sh[t]) atomicAdd(&g_hist[t], sh[t]);
    if (t == 0 && sval) atomicAdd(&g_nvalid, sval);
}

// One radix digit selection step over the 256-bin histogram.
// first=1: also computes n_keep from n_valid (matches jax f32 truncation).
__global__ void select_kernel(int first) {
    __shared__ unsigned int h[256];
    const int t = threadIdx.x;
    h[t] = g_hist[t];
    __syncthreads();

    unsigned int k;
    if (first) {
        const unsigned int nv = g_nvalid;
        int nk = (int)(0.7f * (float)nv);     // f32 multiply + trunc, as in jax
        if (nk < MIN_KEPT_K) nk = MIN_KEPT_K;
        if ((unsigned int)nk > nv) nk = (int)nv;
        if (nk < 1) nk = 1;                   // guard (fallback path used anyway)
        k = (unsigned int)nk;
    } else {
        k = g_k;
    }

    unsigned int above = 0;
    for (int j = t + 1; j < 256; j++) above += h[j];

    if (above < k && above + h[t] >= k) {     // unique thread (requires h[t] > 0)
        g_prefix = (g_prefix << 8) | (unsigned int)t;
        g_k = k - above;
    }
    g_hist[t] = 0u;                           // ready for next pass
}

// Histogram the next 8-bit digit among elements matching the current prefix.
// shift in {16, 8, 0}; prefix covers bits [31 : shift+8).
__global__ void __launch_bounds__(256) refine_kernel(int shift) {
    __shared__ unsigned int sh[256];
    const int t = threadIdx.x;
    sh[t] = 0u;
    __syncthreads();

    const unsigned int pref = g_prefix;
    const int i = blockIdx.x * 256 + t;       // indexes float4
    const float4 v = reinterpret_cast<const float4*>(g_loss)[i];

    const float a[4] = {v.x, v.y, v.z, v.w};
    #pragma unroll
    for (int j = 0; j < 4; j++) {
        if (a[j] > 0.0f) {
            const unsigned int b = __float_as_uint(a[j]);
            if ((b >> (shift + 8)) == pref)
                atomicAdd(&sh[(b >> shift) & 255u], 1u);
        }
    }
    __syncthreads();
    if (sh[t]) atomicAdd(&g_hist[t], sh[t]);
}

// Sum + count of losses >= exact k-th-largest threshold.
__global__ void __launch_bounds__(256) final_sum_kernel() {
    __shared__ float  wsum[8];
    __shared__ int    wcnt[8];

    const float thresh = __uint_as_float(g_prefix);
    const int t = threadIdx.x;
    const int i = blockIdx.x * 256 + t;
    const float4 v = reinterpret_cast<const float4*>(g_loss)[i];

    float s = 0.0f;
    int   c = 0;
    if (v.x >= thresh) { s += v.x; c++; }
    if (v.y >= thresh) { s += v.y; c++; }
    if (v.z >= thresh) { s += v.z; c++; }
    if (v.w >= thresh) { s += v.w; c++; }

    #pragma unroll
    for (int o = 16; o; o >>= 1) {
        s += __shfl_down_sync(0xffffffffu, s, o);
        c += __shfl_down_sync(0xffffffffu, c, o);
    }
    if ((t & 31) == 0) { wsum[t >> 5] = s; wcnt[t >> 5] = c; }
    __syncthreads();
    if (t < 8) {
        float x  = wsum[t];
        int   cc = wcnt[t];
        #pragma unroll
        for (int o = 4; o; o >>= 1) {
            x  += __shfl_down_sync(0xffu, x, o);
            cc += __shfl_down_sync(0xffu, cc, o);
        }
        if (t == 0) {
            atomicAdd(&g_kept_sum, (double)x);
            atomicAdd(&g_kept_cnt, (unsigned int)cc);
        }
    }
}

__global__ void finalize_kernel(float* __restrict__ out) {
    if (g_nvalid > 0u) {
        unsigned int c = g_kept_cnt;
        if (c == 0u) c = 1u;
        out[0] = (float)(g_kept_sum / (double)c);
    } else {
        out[0] = (float)(g_total_sum / (double)NPIX);
    }
}

// ---------------- entry point ----------------
extern "C" void kernel_launch(void* const* d_in, const int* in_sizes, int n_in,
                              void* d_out, int out_size) {
    const float* logits  = (const float*)d_in[0];
    const int*   targets = (const int*)d_in[1];
    float*       out     = (float*)d_out;

    init_kernel<<<1, 256>>>();
    loss_kernel<<<NPIX / 256, 256>>>(logits, targets);
    select_kernel<<<1, 256>>>(1);
    refine_kernel<<<NPIX / 1024, 256>>>(16);
    select_kernel<<<1, 256>>>(0);
    refine_kernel<<<NPIX / 1024, 256>>>(8);
    select_kernel<<<1, 256>>>(0);
    refine_kernel<<<NPIX / 1024, 256>>>(0);
    select_kernel<<<1, 256>>>(0);
    final_sum_kernel<<<NPIX / 1024, 256>>>();
    finalize_kernel<<<1, 1>>>(out);
}

// round 4
// speedup vs baseline: 1.2418x; 1.2418x over previous
#include <cuda_runtime.h>

// Problem shape (fixed by reference setup_inputs)
#define NC   19
#define HWX  (512 * 1024)     // 524288 = 2^19
#define NPIX (4 * HWX)        // 2097152 = 2^21
#define MIN_KEPT_K 100000

#define LOSS_BLOCKS (NPIX / (256 * 4))    // 2048  (4 pixels / thread)
#define SCAN_BLOCKS (NPIX / (256 * 16))   // 512   (16 elems / thread)

// ---------------- device scratch (no allocations allowed) ----------------
__device__ float        g_loss[NPIX];       // 8 MB loss scratch
__device__ unsigned int g_hist[256];
__device__ unsigned int g_nvalid;
__device__ unsigned int g_prefix;           // radix-select accumulated bits
__device__ unsigned int g_k;                // remaining rank
__device__ double       g_total_sum;        // fallback mean numerator
__device__ double       g_kept_sum;
__device__ unsigned int g_kept_cnt;
__device__ unsigned int g_done[5];          // per-pass last-block counters

// ---------------- init ----------------
__global__ void init_kernel() {
    int t = threadIdx.x;
    g_hist[t] = 0u;
    if (t < 5) g_done[t] = 0u;
    if (t == 0) {
        g_nvalid    = 0u;
        g_prefix    = 0u;
        g_k         = 0u;
        g_total_sum = 0.0;
        g_kept_sum  = 0.0;
        g_kept_cnt  = 0u;
    }
}

// One radix-digit selection over the 256-bin histogram. Runs inside the
// tail of the producing kernel (all 256 threads of the last block).
__device__ void do_select(int first) {
    __shared__ unsigned int h[256];
    __shared__ unsigned int ss[256];
    const int t = threadIdx.x;
    const unsigned int hv = *((volatile unsigned int*)&g_hist[t]);
    h[t]  = hv;
    ss[t] = hv;
    __syncthreads();
    // inclusive suffix sum: ss[t] = sum_{j>=t} h[j]
    #pragma unroll
    for (int off = 1; off < 256; off <<= 1) {
        unsigned int v = (t + off < 256) ? ss[t + off] : 0u;
        __syncthreads();
        ss[t] += v;
        __syncthreads();
    }
    unsigned int k;
    if (first) {
        const unsigned int nv = *((volatile unsigned int*)&g_nvalid);
        int nk = (int)(0.7f * (float)nv);     // f32 mul + trunc, matches jax
        if (nk < MIN_KEPT_K) nk = MIN_KEPT_K;
        if ((unsigned int)nk > nv) nk = (int)nv;
        if (nk < 1) nk = 1;
        k = (unsigned int)nk;
    } else {
        k = g_k;
    }
    const unsigned int incl  = ss[t];
    const unsigned int above = incl - h[t];
    if (above < k && incl >= k) {             // unique thread (h[t] > 0)
        g_prefix = (g_prefix << 8) | (unsigned int)t;
        g_k = k - above;
    }
    g_hist[t] = 0u;                           // ready for next pass
}

// Fused: per-pixel NLL, loss scratch write, validity count, fallback sum,
// top-8-bit histogram, and (in the last block) the first radix select.
__global__ void __launch_bounds__(256) loss_kernel(
    const float* __restrict__ logits,
    const int* __restrict__ targets)          // int32 (jax x64 disabled)
{
    __shared__ unsigned int sh[256];
    __shared__ unsigned int sval;
    __shared__ float wsum[8];
    __shared__ bool  lastf;

    const int t = threadIdx.x;
    sh[t] = 0u;
    if (t == 0) sval = 0u;
    __syncthreads();

    const int p  = (blockIdx.x * 256 + t) * 4;     // first of 4 pixels
    const int n  = p >> 19;
    const int hw = p & (HWX - 1);
    const float* base = logits + ((size_t)n * NC) * HWX + hw;

    const int4 tg = *reinterpret_cast<const int4*>(targets + p);

    float4 s  = make_float4(0.f, 0.f, 0.f, 0.f);
    float4 xt = make_float4(0.f, 0.f, 0.f, 0.f);   // tg in [0,NC) -> set once
    #pragma unroll
    for (int c = 0; c < NC; c++) {
        const float4 v = __ldg(reinterpret_cast<const float4*>(base + (size_t)c * HWX));
        s.x += __expf(v.x);  s.y += __expf(v.y);
        s.z += __expf(v.z);  s.w += __expf(v.w);
        xt.x = (tg.x == c) ? v.x : xt.x;
        xt.y = (tg.y == c) ? v.y : xt.y;
        xt.z = (tg.z == c) ? v.z : xt.z;
        xt.w = (tg.w == c) ? v.w : xt.w;
    }

    float l0 = __logf(s.x) - xt.x;
    float l1 = __logf(s.y) - xt.y;
    float l2 = __logf(s.z) - xt.z;
    float l3 = __logf(s.w) - xt.w;

    *reinterpret_cast<float4*>(&g_loss[p]) = make_float4(l0, l1, l2, l3);

    unsigned int cnt = 0;
    if (l0 > 0.0f) { atomicAdd(&sh[__float_as_uint(l0) >> 24], 1u); cnt++; }
    if (l1 > 0.0f) { atomicAdd(&sh[__float_as_uint(l1) >> 24], 1u); cnt++; }
    if (l2 > 0.0f) { atomicAdd(&sh[__float_as_uint(l2) >> 24], 1u); cnt++; }
    if (l3 > 0.0f) { atomicAdd(&sh[__float_as_uint(l3) >> 24], 1u); cnt++; }
    if (cnt) atomicAdd(&sval, cnt);

    // block-reduce total sum (n_valid == 0 fallback path)
    float ls = l0 + l1 + l2 + l3;
    #pragma unroll
    for (int o = 16; o; o >>= 1) ls += __shfl_down_sync(0xffffffffu, ls, o);
    if ((t & 31) == 0) wsum[t >> 5] = ls;
    __syncthreads();
    if (t < 8) {
        float x = wsum[t];
        #pragma unroll
        for (int o = 4; o; o >>= 1) x += __shfl_down_sync(0xffu, x, o);
        if (t == 0) atomicAdd(&g_total_sum, (double)x);
    }

    if (sh[t]) atomicAdd(&g_hist[t], sh[t]);
    if (t == 0 && sval) atomicAdd(&g_nvalid, sval);

    // last-block-done tail -> fused select
    __threadfence();
    __syncthreads();
    if (t == 0) lastf = (atomicAdd(&g_done[0], 1u) == (unsigned)(LOSS_BLOCKS - 1));
    __syncthreads();
    if (lastf) { __threadfence(); do_select(1); }
}

// Histogram the next 8-bit digit among elements matching the current prefix,
// then (last block) fused select. shift in {16, 8, 0}.
__global__ void __launch_bounds__(256) refine_kernel(int shift, int pass) {
    __shared__ unsigned int sh[256];
    __shared__ bool lastf;
    const int t = threadIdx.x;
    sh[t] = 0u;
    __syncthreads();

    const unsigned int pref = g_prefix;
    const int base4 = blockIdx.x * (256 * 4);       // in float4 units
    #pragma unroll
    for (int j = 0; j < 4; j++) {
        const float4 v = reinterpret_cast<const float4*>(g_loss)[base4 + j * 256 + t];
        const float a[4] = {v.x, v.y, v.z, v.w};
        #pragma unroll
        for (int e = 0; e < 4; e++) {
            if (a[e] > 0.0f) {
                const unsigned int b = __float_as_uint(a[e]);
                if ((b >> (shift + 8)) == pref)
                    atomicAdd(&sh[(b >> shift) & 255u], 1u);
            }
        }
    }
    __syncthreads();
    if (sh[t]) atomicAdd(&g_hist[t], sh[t]);

    __threadfence();
    __syncthreads();
    if (t == 0) lastf = (atomicAdd(&g_done[pass], 1u) == (unsigned)(SCAN_BLOCKS - 1));
    __syncthreads();
    if (lastf) { __threadfence(); do_select(0); }
}

// Sum + count of losses >= exact k-th-largest threshold; last block finalizes.
__global__ void __launch_bounds__(256) final_sum_kernel(float* __restrict__ out) {
    __shared__ float  wsum[8];
    __shared__ int    wcnt[8];
    __shared__ bool   lastf;

    const float thresh = __uint_as_float(g_prefix);
    const int t = threadIdx.x;
    const int base4 = blockIdx.x * (256 * 4);

    float s = 0.0f;
    int   c = 0;
    #pragma unroll
    for (int j = 0; j < 4; j++) {
        const float4 v = reinterpret_cast<const float4*>(g_loss)[base4 + j * 256 + t];
        if (v.x >= thresh) { s += v.x; c++; }
        if (v.y >= thresh) { s += v.y; c++; }
        if (v.z >= thresh) { s += v.z; c++; }
        if (v.w >= thresh) { s += v.w; c++; }
    }

    #pragma unroll
    for (int o = 16; o; o >>= 1) {
        s += __shfl_down_sync(0xffffffffu, s, o);
        c += __shfl_down_sync(0xffffffffu, c, o);
    }
    if ((t & 31) == 0) { wsum[t >> 5] = s; wcnt[t >> 5] = c; }
    __syncthreads();
    if (t < 8) {
        float x  = wsum[t];
        int   cc = wcnt[t];
        #pragma unroll
        for (int o = 4; o; o >>= 1) {
            x  += __shfl_down_sync(0xffu, x, o);
            cc += __shfl_down_sync(0xffu, cc, o);
        }
        if (t == 0) {
            atomicAdd(&g_kept_sum, (double)x);
            atomicAdd(&g_kept_cnt, (unsigned int)cc);
        }
    }

    __threadfence();
    __syncthreads();
    if (t == 0) lastf = (atomicAdd(&g_done[4], 1u) == (unsigned)(SCAN_BLOCKS - 1));
    __syncthreads();
    if (lastf && t == 0) {
        __threadfence();
        const unsigned int nv = *((volatile unsigned int*)&g_nvalid);
        if (nv > 0u) {
            unsigned int kc = *((volatile unsigned int*)&g_kept_cnt);
            if (kc == 0u) kc = 1u;
            const double ks = *((volatile double*)&g_kept_sum);
            out[0] = (float)(ks / (double)kc);
        } else {
            const double ts = *((volatile double*)&g_total_sum);
            out[0] = (float)(ts / (double)NPIX);
        }
    }
}

// ---------------- entry point ----------------
extern "C" void kernel_launch(void* const* d_in, const int* in_sizes, int n_in,
                              void* d_out, int out_size) {
    const float* logits  = (const float*)d_in[0];
    const int*   targets = (const int*)d_in[1];
    float*       out     = (float*)d_out;

    init_kernel<<<1, 256>>>();
    loss_kernel<<<LOSS_BLOCKS, 256>>>(logits, targets);
    refine_kernel<<<SCAN_BLOCKS, 256>>>(16, 1);
    refine_kernel<<<SCAN_BLOCKS, 256>>>(8, 2);
    refine_kernel<<<SCAN_BLOCKS, 256>>>(0, 3);
    final_sum_kernel<<<SCAN_BLOCKS, 256>>>(out);
}